// round 7
// baseline (speedup 1.0000x reference)
#include <cuda_runtime.h>
#include <cuda_bf16.h>
#include <stdint.h>

// Problem constants
#define NN 8192      // nodes
#define SS 8192      // structures
#define FF 64        // features
#define OO 64        // out features
#define K0c 0.5f
#define K1c 0.05f
#define K2c (-0.05f)
#define K3c 0.05f

// ---------------------------------------------------------------------------
// Device scratch (static allocation — allowed)
// ---------------------------------------------------------------------------
__device__ __nv_bfloat16 g_xThi[FF * NN];   // x^T split hi  [f][k]
__device__ __nv_bfloat16 g_xTlo[FF * NN];   // x^T split lo  [f][k]
__device__ float g_ypart[16][NN * FF];      // [mat*8 + ksplit][n][f]
__device__ int   g_cnt[SS];
__device__ int   g_members[SS * 10];
__device__ float g_acc2[NN * FF];

// ---------------------------------------------------------------------------
// portable PTX helpers (no sm_103a-only features)
// ---------------------------------------------------------------------------
#define LDSM_X4(r0, r1, r2, r3, addr) \
    asm volatile("ldmatrix.sync.aligned.m8n8.x4.shared.b16 {%0,%1,%2,%3}, [%4];" \
                 : "=r"(r0), "=r"(r1), "=r"(r2), "=r"(r3) : "r"(addr))

#define MMA16816(c, a, b0, b1) \
    asm volatile("mma.sync.aligned.m16n8k16.row.col.f32.bf16.bf16.f32 " \
                 "{%0,%1,%2,%3}, {%4,%5,%6,%7}, {%8,%9}, {%0,%1,%2,%3};" \
                 : "+f"((c)[0]), "+f"((c)[1]), "+f"((c)[2]), "+f"((c)[3]) \
                 : "r"((a)[0]), "r"((a)[1]), "r"((a)[2]), "r"((a)[3]), \
                   "r"(b0), "r"(b1))

#define CP_ASYNC16(dst, src) \
    asm volatile("cp.async.cg.shared.global [%0], [%1], 16;" \
                 :: "r"(dst), "l"(src) : "memory")
#define CP_COMMIT() asm volatile("cp.async.commit_group;" ::: "memory")
#define CP_WAIT2()  asm volatile("cp.async.wait_group 2;" ::: "memory")

#define BAR_SYNC(id, cnt) \
    asm volatile("bar.sync %0, %1;" :: "r"(id), "r"(cnt) : "memory")
#define BAR_ARRIVE(id, cnt) \
    asm volatile("bar.arrive %0, %1;" :: "r"(id), "r"(cnt) : "memory")

__device__ __forceinline__ uint32_t smem_u32(const void* p) {
    return (uint32_t)__cvta_generic_to_shared(p);
}

// ---------------------------------------------------------------------------
// Kernel: zero accumulators (must run every launch; scratch persists)
// ---------------------------------------------------------------------------
__global__ void zero_kernel() {
    int t = blockIdx.x * 256 + threadIdx.x;
    if (t < (NN * FF) / 4) ((float4*)g_acc2)[t] = make_float4(0.f, 0.f, 0.f, 0.f);
    if (t < SS / 4)        ((int4*)g_cnt)[t]   = make_int4(0, 0, 0, 0);
}

// ---------------------------------------------------------------------------
// Kernel: split x into transposed bf16 hi/lo pairs
// ---------------------------------------------------------------------------
__global__ void split_x_kernel(const float* __restrict__ x) {
    int t = blockIdx.x * 256 + threadIdx.x;       // 0 .. NN*FF-1
    int i = t >> 6, f = t & 63;
    float v = x[t];
    __nv_bfloat16 h = __float2bfloat16(v);
    float r = v - __bfloat162float(h);
    g_xThi[f * NN + i] = h;
    g_xTlo[f * NN + i] = __float2bfloat16(r);
}

// ---------------------------------------------------------------------------
// Kernel: per-structure tanh term + scatter into acc2
// ---------------------------------------------------------------------------
__global__ void struct_kernel(const float* __restrict__ x) {
    int wid = threadIdx.x >> 5, lid = threadIdx.x & 31;
    int s = blockIdx.x * 8 + wid;
    int m = g_cnt[s];
    if (m != 3 && m != 4 && m != 10) return;
    int mem[10];
    int first = 0x7FFFFFFF;
#pragma unroll 10
    for (int j = 0; j < 10; j++) {
        if (j < m) {
            mem[j] = g_members[s * 10 + j];
            first = min(first, mem[j]);
        }
    }
    float sa = 0.f, sb = 0.f;
    for (int j = 0; j < m; j++) {
        const float* xr = x + mem[j] * FF;
        sa += xr[lid];
        sb += xr[lid + 32];
    }
    const float* xf = x + first * FF;
    float fm = (float)m;
    float ta = tanhf(fm * xf[lid]      - sa) * K3c;
    float tb = tanhf(fm * xf[lid + 32] - sb) * K3c;
    for (int j = 0; j < m; j++) {
        atomicAdd(&g_acc2[mem[j] * FF + lid],      ta);
        atomicAdd(&g_acc2[mem[j] * FF + 32 + lid], tb);
    }
}

// ---------------------------------------------------------------------------
// Fused warp-specialized GEMM + incidence extraction.
// Warps 0-3: MMA consumers.  Warps 4-7: producers (cp.async, A split, extract).
// BM=64, BN=64, TKC=32, 4 stages, 2 CTAs/SM. grid = 2048.
// ---------------------------------------------------------------------------
#define TKC 32
#define KSPLIT 8
#define KPER (NN / KSPLIT)          // 1024
#define GITERS (KPER / TKC)         // 32
#define NSTAGE 4
// stage layout (bytes)
#define AF_ROW_B 144                // 128B fp32 row + 16B pad (bank shift)
#define AF_OFF   0                  // A fp32: 64 x 144 = 9216
#define AHI_OFF  9216               // A bf16 hi: 64 x 64B = 4096
#define ALO_OFF  13312
#define BHI_OFF  17408
#define BLO_OFF  21504
#define STAGE_BYTES 25600
#define GEMM_SMEM (NSTAGE * STAGE_BYTES)   // 102400

// named barriers
#define FULL_B  1
#define EMPTY_B 5
#define PROD_B  9

// SW64 swizzle for 64B rows: 16B chunk c at row r -> c ^ ((r>>1)&3)
#define SW64C(r, c) ((((c) ^ (((r) >> 1) & 3))) << 4)

__device__ __forceinline__ void splitf2(float2 v, uint32_t& h, uint32_t& l) {
    __nv_bfloat162 hh = __float22bfloat162_rn(v);
    float hx = __bfloat162float(__low2bfloat16(hh));
    float hy = __bfloat162float(__high2bfloat16(hh));
    __nv_bfloat162 ll = __floats2bfloat162_rn(v.x - hx, v.y - hy);
    h = *(uint32_t*)&hh;
    l = *(uint32_t*)&ll;
}

__global__ void __launch_bounds__(256, 2)
gemm_ws_kernel(const float* __restrict__ lapP, const float* __restrict__ lapN,
               const float* __restrict__ inc) {
    extern __shared__ char smem[];
    const int tid = threadIdx.x;
    const int wid = tid >> 5;
    const int lane = tid & 31;
    const int bid = blockIdx.x;
    const int mat = bid >> 10;
    const int rest = bid & 1023;
    const int ks = rest & 7;
    const int mtile = rest >> 3;
    const float* A = mat ? lapN : lapP;
    float* dst = g_ypart[mat * 8 + ks];
    const int m0 = mtile * 64;
    const int kb = ks * KPER;
    const uint32_t sbase = smem_u32(smem);

    if (wid >= 4) {
        // =========================== PRODUCER ===========================
        const int pl = tid & 127;
        const float4* inc4 = (const float4*)inc;
        const int inc_base = bid * 8192;

        for (int ii = 0; ii < GITERS + 2; ++ii) {
            if (ii < GITERS) {
                const int s = ii & (NSTAGE - 1);
                if (ii >= NSTAGE) BAR_SYNC(EMPTY_B + s, 256);
                const uint32_t st = sbase + s * STAGE_BYTES;
                const int k0 = kb + ii * TKC;
                // A fp32: 64 rows x 128B = 512 chunks, 4/lane
#pragma unroll
                for (int j = 0; j < 4; j++) {
                    int q = pl + j * 128;
                    int row = q >> 3, c = q & 7;
                    CP_ASYNC16(st + AF_OFF + row * AF_ROW_B + c * 16,
                               A + (size_t)(m0 + row) * NN + k0 + c * 4);
                }
                // B hi/lo: 64 rows x 64B SW64 = 256 chunks each, 2/lane
#pragma unroll
                for (int j = 0; j < 2; j++) {
                    int q = pl + j * 128;
                    int row = q >> 2, c = q & 3;
                    uint32_t sw = (uint32_t)(row * 64 + SW64C(row, c));
                    CP_ASYNC16(st + BHI_OFF + sw,
                               g_xThi + (size_t)row * NN + k0 + c * 8);
                    CP_ASYNC16(st + BLO_OFF + sw,
                               g_xTlo + (size_t)row * NN + k0 + c * 8);
                }
                // fused incidence extraction: 2 float4 per lane per iter
#pragma unroll
                for (int j = 0; j < 2; j++) {
                    int q = inc_base + ii * 256 + j * 128 + pl;
                    float4 v = __ldcs(inc4 + q);
                    int e = q * 4;
                    int i = e >> 13;        // node row
                    int sc = e & 8191;      // structure col
                    float vv[4] = {v.x, v.y, v.z, v.w};
#pragma unroll
                    for (int u = 0; u < 4; u++) {
                        if (vv[u] != 0.0f) {
                            int p = atomicAdd(&g_cnt[sc + u], 1);
                            if (p < 10) g_members[(sc + u) * 10 + p] = i;
                        }
                    }
                }
            }
            CP_COMMIT();                    // one group per ii (empty at tail)
            if (ii >= 2) {
                const int t = (ii - 2) & (NSTAGE - 1);
                CP_WAIT2();                 // group ii-2 complete
                BAR_SYNC(PROD_B, 128);      // cross-lane visibility of cp.async
                const char* sa = smem + t * STAGE_BYTES;
                char* sd = smem + t * STAGE_BYTES;
                const int r = pl >> 1, h = pl & 1;
                const char* p = sa + AF_OFF + r * AF_ROW_B + h * 64;
                float4 w0 = *(const float4*)(p);
                float4 w1 = *(const float4*)(p + 16);
                float4 w2 = *(const float4*)(p + 32);
                float4 w3 = *(const float4*)(p + 48);
                uint32_t hi[8], lo[8];
                splitf2(make_float2(w0.x, w0.y), hi[0], lo[0]);
                splitf2(make_float2(w0.z, w0.w), hi[1], lo[1]);
                splitf2(make_float2(w1.x, w1.y), hi[2], lo[2]);
                splitf2(make_float2(w1.z, w1.w), hi[3], lo[3]);
                splitf2(make_float2(w2.x, w2.y), hi[4], lo[4]);
                splitf2(make_float2(w2.z, w2.w), hi[5], lo[5]);
                splitf2(make_float2(w3.x, w3.y), hi[6], lo[6]);
                splitf2(make_float2(w3.z, w3.w), hi[7], lo[7]);
                const int c0 = 2 * h;
                char* dh = sd + AHI_OFF + r * 64;
                char* dl = sd + ALO_OFF + r * 64;
                *(uint4*)(dh + SW64C(r, c0))     = make_uint4(hi[0], hi[1], hi[2], hi[3]);
                *(uint4*)(dh + SW64C(r, c0 + 1)) = make_uint4(hi[4], hi[5], hi[6], hi[7]);
                *(uint4*)(dl + SW64C(r, c0))     = make_uint4(lo[0], lo[1], lo[2], lo[3]);
                *(uint4*)(dl + SW64C(r, c0 + 1)) = make_uint4(lo[4], lo[5], lo[6], lo[7]);
                BAR_ARRIVE(FULL_B + t, 256);
            }
        }
    } else {
        // =========================== CONSUMER ===========================
        const int warp_m = (wid & 1) * 32;
        const int warp_n = (wid >> 1) * 32;

        float acc[2][4][4];
#pragma unroll
        for (int mt = 0; mt < 2; mt++)
#pragma unroll
            for (int nt = 0; nt < 4; nt++)
#pragma unroll
                for (int j = 0; j < 4; j++) acc[mt][nt][j] = 0.f;

        for (int it = 0; it < GITERS; ++it) {
            const int t = it & (NSTAGE - 1);
            BAR_SYNC(FULL_B + t, 256);
            const uint32_t st = sbase + t * STAGE_BYTES;
#pragma unroll
            for (int kc = 0; kc < 2; kc++) {
                uint32_t ah[2][4], al[2][4];
#pragma unroll
                for (int mt = 0; mt < 2; mt++) {
                    uint32_t row = warp_m + mt * 16 + (lane & 15);
                    uint32_t c = kc * 2 + (lane >> 4);
                    uint32_t off = row * 64 + SW64C(row, c);
                    LDSM_X4(ah[mt][0], ah[mt][1], ah[mt][2], ah[mt][3],
                            st + AHI_OFF + off);
                    LDSM_X4(al[mt][0], al[mt][1], al[mt][2], al[mt][3],
                            st + ALO_OFF + off);
                }
                uint32_t bh[2][4], bl[2][4];
#pragma unroll
                for (int nt2 = 0; nt2 < 2; nt2++) {
                    uint32_t grp = lane >> 3;
                    uint32_t nrow = warp_n + nt2 * 16 + (grp >> 1) * 8 + (lane & 7);
                    uint32_t c = kc * 2 + (grp & 1);
                    uint32_t off = nrow * 64 + SW64C(nrow, c);
                    LDSM_X4(bh[nt2][0], bh[nt2][1], bh[nt2][2], bh[nt2][3],
                            st + BHI_OFF + off);
                    LDSM_X4(bl[nt2][0], bl[nt2][1], bl[nt2][2], bl[nt2][3],
                            st + BLO_OFF + off);
                }
#pragma unroll
                for (int mt = 0; mt < 2; mt++) {
#pragma unroll
                    for (int nt = 0; nt < 4; nt++) {
                        int n2 = nt >> 1, p = (nt & 1) * 2;
                        MMA16816(acc[mt][nt], ah[mt], bh[n2][p], bh[n2][p + 1]);
                        MMA16816(acc[mt][nt], ah[mt], bl[n2][p], bl[n2][p + 1]);
                        MMA16816(acc[mt][nt], al[mt], bh[n2][p], bh[n2][p + 1]);
                    }
                }
            }
            BAR_ARRIVE(EMPTY_B + t, 256);
        }

        // epilogue: write partial results
#pragma unroll
        for (int mt = 0; mt < 2; mt++) {
#pragma unroll
            for (int nt = 0; nt < 4; nt++) {
                int r0 = m0 + warp_m + mt * 16 + (lane >> 2);
                int c0 = warp_n + nt * 8 + (lane & 3) * 2;
                *(float2*)(dst + (size_t)r0 * FF + c0) =
                    make_float2(acc[mt][nt][0], acc[mt][nt][1]);
                *(float2*)(dst + (size_t)(r0 + 8) * FF + c0) =
                    make_float2(acc[mt][nt][2], acc[mt][nt][3]);
            }
        }
    }
}

// ---------------------------------------------------------------------------
// Final fused kernel: out = (K0*x + K1*sin(yp) + K2*sin(yn) + acc2) @ W + bias
// ---------------------------------------------------------------------------
__global__ void final_kernel(const float* __restrict__ x, const float* __restrict__ w,
                             const float* __restrict__ bias, float* __restrict__ out) {
    __shared__ float wsm[FF * OO];
    __shared__ float vsm[4 * FF];
    int tid = threadIdx.x;
#pragma unroll
    for (int j = 0; j < 16; j++) wsm[tid + j * 256] = w[tid + j * 256];
    int r = tid >> 6, f = tid & 63;
    int i = blockIdx.x * 4 + r;
    int idx = i * FF + f;
    float yp = 0.f, yn = 0.f;
#pragma unroll
    for (int p = 0; p < 8; p++) yp += g_ypart[p][idx];
#pragma unroll
    for (int p = 8; p < 16; p++) yn += g_ypart[p][idx];
    float v = K0c * x[idx] + K1c * sinf(yp) + K2c * sinf(yn) + g_acc2[idx];
    vsm[r * FF + f] = v;
    __syncthreads();
    int o = f;
    float acc = bias[o];
#pragma unroll
    for (int ff = 0; ff < FF; ff++)
        acc += vsm[r * FF + ff] * wsm[ff * OO + o];
    out[i * OO + o] = acc;
}

// ---------------------------------------------------------------------------
// Launch
// ---------------------------------------------------------------------------
extern "C" void kernel_launch(void* const* d_in, const int* in_sizes, int n_in,
                              void* d_out, int out_size) {
    const float* x    = (const float*)d_in[0];
    const float* lapP = (const float*)d_in[1];
    const float* lapN = (const float*)d_in[2];
    const float* inc  = (const float*)d_in[3];
    const float* w    = (const float*)d_in[4];
    const float* bias = (const float*)d_in[5];
    float* out = (float*)d_out;

    cudaFuncSetAttribute(gemm_ws_kernel,
                         cudaFuncAttributeMaxDynamicSharedMemorySize, GEMM_SMEM);

    zero_kernel<<<512, 256>>>();
    split_x_kernel<<<(NN * FF) / 256, 256>>>(x);
    gemm_ws_kernel<<<2048, 256, GEMM_SMEM>>>(lapP, lapN, inc);
    struct_kernel<<<SS / 8, 256>>>(x);
    final_kernel<<<NN / 4, 256>>>(x, w, bias, out);
}

// round 8
// speedup vs baseline: 1.3700x; 1.3700x over previous
#include <cuda_runtime.h>
#include <cuda_bf16.h>
#include <stdint.h>

// Problem constants
#define NN 8192      // nodes
#define SS 8192      // structures
#define FF 64        // features
#define OO 64        // out features
#define K0c 0.5f
#define K1c 0.05f
#define K2c (-0.05f)
#define K3c 0.05f

// ---------------------------------------------------------------------------
// Device scratch (static allocation — allowed)
// ---------------------------------------------------------------------------
__device__ __nv_bfloat16 g_xThi[FF * NN];   // x^T split hi  [f][k]
__device__ __nv_bfloat16 g_xTlo[FF * NN];   // x^T split lo  [f][k]
__device__ float g_ypart[16][NN * FF];      // [mat*8 + ksplit][n][f]
__device__ int   g_cnt[SS];
__device__ int   g_members[SS * 10];
__device__ float g_acc2[NN * FF];
__device__ unsigned int g_job;

// ---------------------------------------------------------------------------
// portable PTX helpers (no sm_103a-only features)
// ---------------------------------------------------------------------------
#define LDSM_X4(r0, r1, r2, r3, addr) \
    asm volatile("ldmatrix.sync.aligned.m8n8.x4.shared.b16 {%0,%1,%2,%3}, [%4];" \
                 : "=r"(r0), "=r"(r1), "=r"(r2), "=r"(r3) : "r"(addr))

#define MMA16816(c, a, b0, b1) \
    asm volatile("mma.sync.aligned.m16n8k16.row.col.f32.bf16.bf16.f32 " \
                 "{%0,%1,%2,%3}, {%4,%5,%6,%7}, {%8,%9}, {%0,%1,%2,%3};" \
                 : "+f"((c)[0]), "+f"((c)[1]), "+f"((c)[2]), "+f"((c)[3]) \
                 : "r"((a)[0]), "r"((a)[1]), "r"((a)[2]), "r"((a)[3]), \
                   "r"(b0), "r"(b1))

#define CP_ASYNC16(dst, src) \
    asm volatile("cp.async.cg.shared.global [%0], [%1], 16;" \
                 :: "r"(dst), "l"(src) : "memory")
#define CP_COMMIT() asm volatile("cp.async.commit_group;" ::: "memory")
#define CP_WAIT1()  asm volatile("cp.async.wait_group 1;" ::: "memory")
#define CP_WAIT0()  asm volatile("cp.async.wait_group 0;" ::: "memory")

__device__ __forceinline__ uint32_t smem_u32(const void* p) {
    return (uint32_t)__cvta_generic_to_shared(p);
}

// ---------------------------------------------------------------------------
// Kernel: split x into transposed bf16 hi/lo pairs + zero accumulators/queue
// ---------------------------------------------------------------------------
__global__ void split_x_kernel(const float* __restrict__ x) {
    int t = blockIdx.x * 256 + threadIdx.x;       // 0 .. NN*FF-1
    int i = t >> 6, f = t & 63;
    float v = x[t];
    __nv_bfloat16 h = __float2bfloat16(v);
    float r = v - __bfloat162float(h);
    g_xThi[f * NN + i] = h;
    g_xTlo[f * NN + i] = __float2bfloat16(r);
    g_acc2[t] = 0.f;                              // same element count
    if (t < SS) g_cnt[t] = 0;
    if (t == 0) g_job = 0u;
}

// ---------------------------------------------------------------------------
// Kernel: per-structure tanh term + scatter into acc2
// ---------------------------------------------------------------------------
__global__ void struct_kernel(const float* __restrict__ x) {
    int wid = threadIdx.x >> 5, lid = threadIdx.x & 31;
    int s = blockIdx.x * 8 + wid;
    int m = g_cnt[s];
    if (m != 3 && m != 4 && m != 10) return;
    int mem[10];
    int first = 0x7FFFFFFF;
#pragma unroll 10
    for (int j = 0; j < 10; j++) {
        if (j < m) {
            mem[j] = g_members[s * 10 + j];
            first = min(first, mem[j]);
        }
    }
    float sa = 0.f, sb = 0.f;
    for (int j = 0; j < m; j++) {
        const float* xr = x + mem[j] * FF;
        sa += xr[lid];
        sb += xr[lid + 32];
    }
    const float* xf = x + first * FF;
    float fm = (float)m;
    float ta = tanhf(fm * xf[lid]      - sa) * K3c;
    float tb = tanhf(fm * xf[lid + 32] - sb) * K3c;
    for (int j = 0; j < m; j++) {
        atomicAdd(&g_acc2[mem[j] * FF + lid],      ta);
        atomicAdd(&g_acc2[mem[j] * FF + 32 + lid], tb);
    }
}

// ---------------------------------------------------------------------------
// Persistent fused GEMM + incidence extraction.
// 2048 jobs (128 mtiles x 8 ksplits x 2 matrices), pulled from a global
// atomic queue by 592 persistent CTAs (4/SM, 128 threads).
// Per job: BM=64, BN=64, TKC=32, cp.async 3-stage pipe, bf16-split 3-term MMA.
// ---------------------------------------------------------------------------
#define TKC 32
#define KSPLIT 8
#define KPER (NN / KSPLIT)          // 1024
#define GITERS (KPER / TKC)         // 32
#define NSTAGE 3
// stage: A fp32 64 rows x 160B = 10240; Bhi 64x64B = 4096; Blo 4096
#define A_ROW_B 160
#define B_OFF   10240
#define BL_OFF  14336
#define STAGE_BYTES 18432
#define GEMM_SMEM (NSTAGE * STAGE_BYTES + 16)   // +16: job broadcast slot
#define NJOBS 2048

// SW64 swizzle for 64B rows: chunk c (16B) at row r -> c ^ ((r>>1)&3)
#define SW64C(r, c) (((c) ^ (((r) >> 1) & 3)) << 4)

// truncation split: ah = a with low 16 mantissa bits cleared (1 PRMT for the
// packed pair), al = rn_bf16(a - ah) (2 FADD + 1 CVT)
__device__ __forceinline__ void split_trunc2(float2 v, uint32_t& h, uint32_t& l) {
    uint32_t r0 = __float_as_uint(v.x), r1 = __float_as_uint(v.y);
    uint32_t hp;
    asm("prmt.b32 %0, %1, %2, 0x7632;" : "=r"(hp) : "r"(r0), "r"(r1));
    float a0 = __uint_as_float(r0 & 0xFFFF0000u);
    float a1 = __uint_as_float(r1 & 0xFFFF0000u);
    __nv_bfloat162 ll = __floats2bfloat162_rn(v.x - a0, v.y - a1);
    h = hp;
    l = *(uint32_t*)&ll;
}

__device__ __forceinline__ void issue_stage(const float* __restrict__ A,
                                            int m0, int k0, int tid,
                                            uint32_t sstage) {
    // A: 64 rows x 32 fp32 (128B = 8 x 16B chunks) -> 512 chunks, 4/thread
#pragma unroll
    for (int j = 0; j < 4; j++) {
        int q = tid + j * 128;
        int row = q >> 3, c = q & 7;
        uint32_t dst = sstage + row * A_ROW_B + c * 16;
        const float* src = A + (size_t)(m0 + row) * NN + k0 + c * 4;
        CP_ASYNC16(dst, src);
    }
    // B hi/lo: 64 rows x 32 bf16 = 64B/row, SW64 packed -> 256 chunks each
#pragma unroll
    for (int j = 0; j < 2; j++) {
        int q = tid + j * 128;
        int row = q >> 2, c = q & 3;
        uint32_t sw = (uint32_t)(row * 64 + SW64C(row, c));
        const char* srch = (const char*)(g_xThi + (size_t)row * NN + k0 + c * 8);
        const char* srcl = (const char*)(g_xTlo + (size_t)row * NN + k0 + c * 8);
        CP_ASYNC16(sstage + B_OFF + sw, srch);
        CP_ASYNC16(sstage + BL_OFF + sw, srcl);
    }
    CP_COMMIT();
}

__global__ void __launch_bounds__(128, 4)
gemm_persist_kernel(const float* __restrict__ lapP, const float* __restrict__ lapN,
                    const float* __restrict__ inc) {
    extern __shared__ char smem[];
    const int tid = threadIdx.x;
    const int wid = tid >> 5;
    const int lane = tid & 31;
    const uint32_t sbase = smem_u32(smem);
    int* jobslot = (int*)(smem + NSTAGE * STAGE_BYTES);

    const int warp_m = (wid & 1) * 32;   // 2 warps along M
    const int warp_n = (wid >> 1) * 32;  // 2 warps along N

    for (;;) {
        // ---- claim next job ----
        if (tid == 0) *jobslot = (int)atomicAdd(&g_job, 1u);
        __syncthreads();
        const int job = *jobslot;
        __syncthreads();
        if (job >= NJOBS) break;

        const int mat = job >> 10;
        const int rest = job & 1023;
        const int ks = rest & 7;
        const int mtile = rest >> 3;
        const float* A = mat ? lapN : lapP;
        float* dst = g_ypart[mat * 8 + ks];
        const int m0 = mtile * 64;
        const int kb = ks * KPER;

        float acc[2][4][4];
#pragma unroll
        for (int mt = 0; mt < 2; mt++)
#pragma unroll
            for (int nt = 0; nt < 4; nt++)
#pragma unroll
                for (int j = 0; j < 4; j++) acc[mt][nt][j] = 0.f;

        // prologue: issue first NSTAGE-1 stages
        issue_stage(A, m0, kb, tid, sbase);
        issue_stage(A, m0, kb + TKC, tid, sbase + STAGE_BYTES);

        // ---- fused incidence extraction: this job's 8192-float4 slice ----
        {
            const float4* inc4 = (const float4*)inc;
            int base = job * 8192;
            for (int j = 0; j < 64; j++) {
                int q = base + j * 128 + tid;
                float4 v = __ldcs(inc4 + q);
                int e = q * 4;
                int i = e >> 13;        // node row
                int s = e & 8191;       // structure col
                float vv[4] = {v.x, v.y, v.z, v.w};
#pragma unroll
                for (int u = 0; u < 4; u++) {
                    if (vv[u] != 0.0f) {
                        int p = atomicAdd(&g_cnt[s + u], 1);
                        if (p < 10) g_members[(s + u) * 10 + p] = i;
                    }
                }
            }
        }

        // ---- GEMM mainloop ----
        for (int it = 0; it < GITERS; ++it) {
            CP_WAIT1();            // 2 groups pending -> stage `it` resident
            __syncthreads();

            if (it + NSTAGE - 1 < GITERS)
                issue_stage(A, m0, kb + (it + NSTAGE - 1) * TKC, tid,
                            sbase + ((it + NSTAGE - 1) % NSTAGE) * STAGE_BYTES);
            else
                CP_COMMIT();       // empty group keeps pending count at 2

            const uint32_t sstage = sbase + (it % NSTAGE) * STAGE_BYTES;
            const char* sa = smem + (it % NSTAGE) * STAGE_BYTES;

#pragma unroll
            for (int kc = 0; kc < 2; kc++) {
                // ---- A fragments: LDS fp32 + truncation split ----
                uint32_t ah[2][4], al[2][4];
#pragma unroll
                for (int mt = 0; mt < 2; mt++) {
                    int row0 = warp_m + mt * 16 + (lane >> 2);
                    int kbyt = kc * 64 + (lane & 3) * 8;
                    const char* p = sa + row0 * A_ROW_B + kbyt;
                    float2 v0 = *(const float2*)(p);
                    float2 v1 = *(const float2*)(p + 8 * A_ROW_B);
                    float2 v2 = *(const float2*)(p + 32);
                    float2 v3 = *(const float2*)(p + 8 * A_ROW_B + 32);
                    split_trunc2(v0, ah[mt][0], al[mt][0]);
                    split_trunc2(v1, ah[mt][1], al[mt][1]);
                    split_trunc2(v2, ah[mt][2], al[mt][2]);
                    split_trunc2(v3, ah[mt][3], al[mt][3]);
                }
                // ---- B fragments via ldmatrix from SW64-packed rows ----
                uint32_t bh[2][4], bl[2][4];
#pragma unroll
                for (int nt2 = 0; nt2 < 2; nt2++) {
                    uint32_t grp = lane >> 3;
                    uint32_t nrow = warp_n + nt2 * 16 + (grp >> 1) * 8 + (lane & 7);
                    uint32_t c = kc * 2 + (grp & 1);
                    uint32_t off = nrow * 64 + SW64C(nrow, c);
                    LDSM_X4(bh[nt2][0], bh[nt2][1], bh[nt2][2], bh[nt2][3],
                            sstage + B_OFF + off);
                    LDSM_X4(bl[nt2][0], bl[nt2][1], bl[nt2][2], bl[nt2][3],
                            sstage + BL_OFF + off);
                }
#pragma unroll
                for (int mt = 0; mt < 2; mt++) {
#pragma unroll
                    for (int nt = 0; nt < 4; nt++) {
                        int n2 = nt >> 1, p = (nt & 1) * 2;
                        MMA16816(acc[mt][nt], ah[mt], bh[n2][p], bh[n2][p + 1]);
                        MMA16816(acc[mt][nt], ah[mt], bl[n2][p], bl[n2][p + 1]);
                        MMA16816(acc[mt][nt], al[mt], bh[n2][p], bh[n2][p + 1]);
                    }
                }
            }
        }

        // drain leftover (empty) groups so the next job's invariant holds
        CP_WAIT0();

        // ---- epilogue: write partial results ----
#pragma unroll
        for (int mt = 0; mt < 2; mt++) {
#pragma unroll
            for (int nt = 0; nt < 4; nt++) {
                int r0 = m0 + warp_m + mt * 16 + (lane >> 2);
                int c0 = warp_n + nt * 8 + (lane & 3) * 2;
                *(float2*)(dst + (size_t)r0 * FF + c0) =
                    make_float2(acc[mt][nt][0], acc[mt][nt][1]);
                *(float2*)(dst + (size_t)(r0 + 8) * FF + c0) =
                    make_float2(acc[mt][nt][2], acc[mt][nt][3]);
            }
        }
    }
}

// ---------------------------------------------------------------------------
// Final fused kernel: out = (K0*x + K1*sin(yp) + K2*sin(yn) + acc2) @ W + bias
// ---------------------------------------------------------------------------
__global__ void final_kernel(const float* __restrict__ x, const float* __restrict__ w,
                             const float* __restrict__ bias, float* __restrict__ out) {
    __shared__ float wsm[FF * OO];
    __shared__ float vsm[4 * FF];
    int tid = threadIdx.x;
#pragma unroll
    for (int j = 0; j < 16; j++) wsm[tid + j * 256] = w[tid + j * 256];
    int r = tid >> 6, f = tid & 63;
    int i = blockIdx.x * 4 + r;
    int idx = i * FF + f;
    float yp = 0.f, yn = 0.f;
#pragma unroll
    for (int p = 0; p < 8; p++) yp += g_ypart[p][idx];
#pragma unroll
    for (int p = 8; p < 16; p++) yn += g_ypart[p][idx];
    float v = K0c * x[idx] + K1c * sinf(yp) + K2c * sinf(yn) + g_acc2[idx];
    vsm[r * FF + f] = v;
    __syncthreads();
    int o = f;
    float acc = bias[o];
#pragma unroll
    for (int ff = 0; ff < FF; ff++)
        acc += vsm[r * FF + ff] * wsm[ff * OO + o];
    out[i * OO + o] = acc;
}

// ---------------------------------------------------------------------------
// Launch
// ---------------------------------------------------------------------------
extern "C" void kernel_launch(void* const* d_in, const int* in_sizes, int n_in,
                              void* d_out, int out_size) {
    const float* x    = (const float*)d_in[0];
    const float* lapP = (const float*)d_in[1];
    const float* lapN = (const float*)d_in[2];
    const float* inc  = (const float*)d_in[3];
    const float* w    = (const float*)d_in[4];
    const float* bias = (const float*)d_in[5];
    float* out = (float*)d_out;

    cudaFuncSetAttribute(gemm_persist_kernel,
                         cudaFuncAttributeMaxDynamicSharedMemorySize, GEMM_SMEM);

    split_x_kernel<<<(NN * FF) / 256, 256>>>(x);
    gemm_persist_kernel<<<592, 128, GEMM_SMEM>>>(lapP, lapN, inc);
    struct_kernel<<<SS / 8, 256>>>(x);
    final_kernel<<<NN / 4, 256>>>(x, w, bias, out);
}

// round 9
// speedup vs baseline: 1.3903x; 1.0148x over previous
#include <cuda_runtime.h>
#include <cuda_bf16.h>
#include <stdint.h>

// Problem constants
#define NN 8192      // nodes
#define SS 8192      // structures
#define FF 64        // features
#define OO 64        // out features
#define K0c 0.5f
#define K1c 0.05f
#define K2c (-0.05f)
#define K3c 0.05f

// ---------------------------------------------------------------------------
// Device scratch (static allocation — allowed)
// ---------------------------------------------------------------------------
__device__ __nv_bfloat16 g_xThi[FF * NN];   // x^T split hi  [f][k]
__device__ __nv_bfloat16 g_xTlo[FF * NN];   // x^T split lo  [f][k]
__device__ float g_ypart[16][NN * FF];      // [mat*8 + ksplit][n][f]
__device__ int   g_cnt[SS];
__device__ int   g_members[SS * 10];
__device__ float g_acc2[NN * FF];
__device__ unsigned int g_job;

// ---------------------------------------------------------------------------
// portable PTX helpers (no sm_103a-only features)
// ---------------------------------------------------------------------------
#define LDSM_X4(r0, r1, r2, r3, addr) \
    asm volatile("ldmatrix.sync.aligned.m8n8.x4.shared.b16 {%0,%1,%2,%3}, [%4];" \
                 : "=r"(r0), "=r"(r1), "=r"(r2), "=r"(r3) : "r"(addr))

#define MMA16816(c, a, b0, b1) \
    asm volatile("mma.sync.aligned.m16n8k16.row.col.f32.bf16.bf16.f32 " \
                 "{%0,%1,%2,%3}, {%4,%5,%6,%7}, {%8,%9}, {%0,%1,%2,%3};" \
                 : "+f"((c)[0]), "+f"((c)[1]), "+f"((c)[2]), "+f"((c)[3]) \
                 : "r"((a)[0]), "r"((a)[1]), "r"((a)[2]), "r"((a)[3]), \
                   "r"(b0), "r"(b1))

#define CP_ASYNC16(dst, src) \
    asm volatile("cp.async.cg.shared.global [%0], [%1], 16;" \
                 :: "r"(dst), "l"(src) : "memory")
#define CP_COMMIT() asm volatile("cp.async.commit_group;" ::: "memory")
#define CP_WAIT1()  asm volatile("cp.async.wait_group 1;" ::: "memory")
#define CP_WAIT0()  asm volatile("cp.async.wait_group 0;" ::: "memory")

__device__ __forceinline__ uint32_t smem_u32(const void* p) {
    return (uint32_t)__cvta_generic_to_shared(p);
}

// ---------------------------------------------------------------------------
// Kernel: split x into transposed bf16 hi/lo pairs + zero accumulators/queue
// ---------------------------------------------------------------------------
__global__ void split_x_kernel(const float* __restrict__ x) {
    int t = blockIdx.x * 256 + threadIdx.x;       // 0 .. NN*FF-1
    int i = t >> 6, f = t & 63;
    float v = x[t];
    __nv_bfloat16 h = __float2bfloat16(v);
    float r = v - __bfloat162float(h);
    g_xThi[f * NN + i] = h;
    g_xTlo[f * NN + i] = __float2bfloat16(r);
    g_acc2[t] = 0.f;                              // same element count
    if (t < SS) g_cnt[t] = 0;
    if (t == 0) g_job = 0u;
}

// ---------------------------------------------------------------------------
// Kernel: per-structure tanh term + scatter into acc2
// ---------------------------------------------------------------------------
__global__ void struct_kernel(const float* __restrict__ x) {
    int wid = threadIdx.x >> 5, lid = threadIdx.x & 31;
    int s = blockIdx.x * 8 + wid;
    int m = g_cnt[s];
    if (m != 3 && m != 4 && m != 10) return;
    int mem[10];
    int first = 0x7FFFFFFF;
#pragma unroll 10
    for (int j = 0; j < 10; j++) {
        if (j < m) {
            mem[j] = g_members[s * 10 + j];
            first = min(first, mem[j]);
        }
    }
    float sa = 0.f, sb = 0.f;
    for (int j = 0; j < m; j++) {
        const float* xr = x + mem[j] * FF;
        sa += xr[lid];
        sb += xr[lid + 32];
    }
    const float* xf = x + first * FF;
    float fm = (float)m;
    float ta = tanhf(fm * xf[lid]      - sa) * K3c;
    float tb = tanhf(fm * xf[lid + 32] - sb) * K3c;
    for (int j = 0; j < m; j++) {
        atomicAdd(&g_acc2[mem[j] * FF + lid],      ta);
        atomicAdd(&g_acc2[mem[j] * FF + 32 + lid], tb);
    }
}

// ---------------------------------------------------------------------------
// Persistent fused GEMM + incidence extraction.
// 2048 jobs (128 mtiles x 8 ksplits x 2 matrices), pulled from a global
// atomic queue by 592 persistent CTAs (4/SM, 128 threads).
// Per job: BM=64, BN=64, TKC=32, cp.async 3-stage pipe, bf16-split 3-term MMA.
// ---------------------------------------------------------------------------
#define TKC 32
#define KSPLIT 8
#define KPER (NN / KSPLIT)          // 1024
#define GITERS (KPER / TKC)         // 32
#define NSTAGE 3
// stage: A fp32 64 rows x 160B = 10240; Bhi 64x64B = 4096; Blo 4096
#define A_ROW_B 160
#define B_OFF   10240
#define BL_OFF  14336
#define STAGE_BYTES 18432
#define GEMM_SMEM (NSTAGE * STAGE_BYTES + 16)   // +16: job broadcast slot
#define NJOBS 2048

// SW64 swizzle for 64B rows: chunk c (16B) at row r -> c ^ ((r>>1)&3)
#define SW64C(r, c) (((c) ^ (((r) >> 1) & 3)) << 4)

// truncation split: ah = a with low 16 mantissa bits cleared (1 PRMT for the
// packed pair), al = rn_bf16(a - ah) (2 FADD + 1 CVT)
__device__ __forceinline__ void split_trunc2(float2 v, uint32_t& h, uint32_t& l) {
    uint32_t r0 = __float_as_uint(v.x), r1 = __float_as_uint(v.y);
    uint32_t hp;
    asm("prmt.b32 %0, %1, %2, 0x7632;" : "=r"(hp) : "r"(r0), "r"(r1));
    float a0 = __uint_as_float(r0 & 0xFFFF0000u);
    float a1 = __uint_as_float(r1 & 0xFFFF0000u);
    __nv_bfloat162 ll = __floats2bfloat162_rn(v.x - a0, v.y - a1);
    h = hp;
    l = *(uint32_t*)&ll;
}

__device__ __forceinline__ void issue_stage(const float* __restrict__ A,
                                            int m0, int k0, int tid,
                                            uint32_t sstage) {
    // A: 64 rows x 32 fp32 (128B = 8 x 16B chunks) -> 512 chunks, 4/thread
#pragma unroll
    for (int j = 0; j < 4; j++) {
        int q = tid + j * 128;
        int row = q >> 3, c = q & 7;
        uint32_t dst = sstage + row * A_ROW_B + c * 16;
        const float* src = A + (size_t)(m0 + row) * NN + k0 + c * 4;
        CP_ASYNC16(dst, src);
    }
    // B hi/lo: 64 rows x 32 bf16 = 64B/row, SW64 packed -> 256 chunks each
#pragma unroll
    for (int j = 0; j < 2; j++) {
        int q = tid + j * 128;
        int row = q >> 2, c = q & 3;
        uint32_t sw = (uint32_t)(row * 64 + SW64C(row, c));
        const char* srch = (const char*)(g_xThi + (size_t)row * NN + k0 + c * 8);
        const char* srcl = (const char*)(g_xTlo + (size_t)row * NN + k0 + c * 8);
        CP_ASYNC16(sstage + B_OFF + sw, srch);
        CP_ASYNC16(sstage + BL_OFF + sw, srcl);
    }
    CP_COMMIT();
}

__global__ void __launch_bounds__(128, 4)
gemm_persist_kernel(const float* __restrict__ lapP, const float* __restrict__ lapN,
                    const float* __restrict__ inc) {
    extern __shared__ char smem[];
    const int tid = threadIdx.x;
    const int wid = tid >> 5;
    const int lane = tid & 31;
    const uint32_t sbase = smem_u32(smem);
    int* jobslot = (int*)(smem + NSTAGE * STAGE_BYTES);

    const int warp_m = (wid & 1) * 32;   // 2 warps along M
    const int warp_n = (wid >> 1) * 32;  // 2 warps along N

    for (;;) {
        // ---- claim next job ----
        if (tid == 0) *jobslot = (int)atomicAdd(&g_job, 1u);
        __syncthreads();
        const int job = *jobslot;
        __syncthreads();
        if (job >= NJOBS) break;

        const int mat = job >> 10;
        const int rest = job & 1023;
        const int ks = rest & 7;
        const int mtile = rest >> 3;
        const float* A = mat ? lapN : lapP;
        float* dst = g_ypart[mat * 8 + ks];
        const int m0 = mtile * 64;
        const int kb = ks * KPER;

        float acc[2][4][4];
#pragma unroll
        for (int mt = 0; mt < 2; mt++)
#pragma unroll
            for (int nt = 0; nt < 4; nt++)
#pragma unroll
                for (int j = 0; j < 4; j++) acc[mt][nt][j] = 0.f;

        // prologue: issue first NSTAGE-1 stages
        issue_stage(A, m0, kb, tid, sbase);
        issue_stage(A, m0, kb + TKC, tid, sbase + STAGE_BYTES);

        // ---- fused incidence extraction: this job's 8192-float4 slice ----
        {
            const float4* inc4 = (const float4*)inc;
            int base = job * 8192;
            for (int j = 0; j < 64; j++) {
                int q = base + j * 128 + tid;
                float4 v = __ldcs(inc4 + q);
                int e = q * 4;
                int i = e >> 13;        // node row
                int s = e & 8191;       // structure col
                float vv[4] = {v.x, v.y, v.z, v.w};
#pragma unroll
                for (int u = 0; u < 4; u++) {
                    if (vv[u] != 0.0f) {
                        int p = atomicAdd(&g_cnt[s + u], 1);
                        if (p < 10) g_members[(s + u) * 10 + p] = i;
                    }
                }
            }
        }

        // ---- GEMM mainloop ----
        for (int it = 0; it < GITERS; ++it) {
            CP_WAIT1();            // 2 groups pending -> stage `it` resident
            __syncthreads();

            if (it + NSTAGE - 1 < GITERS)
                issue_stage(A, m0, kb + (it + NSTAGE - 1) * TKC, tid,
                            sbase + ((it + NSTAGE - 1) % NSTAGE) * STAGE_BYTES);
            else
                CP_COMMIT();       // empty group keeps pending count at 2

            const uint32_t sstage = sbase + (it % NSTAGE) * STAGE_BYTES;
            const char* sa = smem + (it % NSTAGE) * STAGE_BYTES;

#pragma unroll
            for (int kc = 0; kc < 2; kc++) {
                // ---- A fragments: LDS fp32 + truncation split ----
                uint32_t ah[2][4], al[2][4];
#pragma unroll
                for (int mt = 0; mt < 2; mt++) {
                    int row0 = warp_m + mt * 16 + (lane >> 2);
                    int kbyt = kc * 64 + (lane & 3) * 8;
                    const char* p = sa + row0 * A_ROW_B + kbyt;
                    float2 v0 = *(const float2*)(p);
                    float2 v1 = *(const float2*)(p + 8 * A_ROW_B);
                    float2 v2 = *(const float2*)(p + 32);
                    float2 v3 = *(const float2*)(p + 8 * A_ROW_B + 32);
                    split_trunc2(v0, ah[mt][0], al[mt][0]);
                    split_trunc2(v1, ah[mt][1], al[mt][1]);
                    split_trunc2(v2, ah[mt][2], al[mt][2]);
                    split_trunc2(v3, ah[mt][3], al[mt][3]);
                }
                // ---- B fragments via ldmatrix from SW64-packed rows ----
                uint32_t bh[2][4], bl[2][4];
#pragma unroll
                for (int nt2 = 0; nt2 < 2; nt2++) {
                    uint32_t grp = lane >> 3;
                    uint32_t nrow = warp_n + nt2 * 16 + (grp >> 1) * 8 + (lane & 7);
                    uint32_t c = kc * 2 + (grp & 1);
                    uint32_t off = nrow * 64 + SW64C(nrow, c);
                    LDSM_X4(bh[nt2][0], bh[nt2][1], bh[nt2][2], bh[nt2][3],
                            sstage + B_OFF + off);
                    LDSM_X4(bl[nt2][0], bl[nt2][1], bl[nt2][2], bl[nt2][3],
                            sstage + BL_OFF + off);
                }
#pragma unroll
                for (int mt = 0; mt < 2; mt++) {
#pragma unroll
                    for (int nt = 0; nt < 4; nt++) {
                        int n2 = nt >> 1, p = (nt & 1) * 2;
                        MMA16816(acc[mt][nt], ah[mt], bh[n2][p], bh[n2][p + 1]);
                        MMA16816(acc[mt][nt], ah[mt], bl[n2][p], bl[n2][p + 1]);
                        MMA16816(acc[mt][nt], al[mt], bh[n2][p], bh[n2][p + 1]);
                    }
                }
            }
        }

        // drain leftover (empty) groups so the next job's invariant holds
        CP_WAIT0();

        // ---- epilogue: write partial results ----
#pragma unroll
        for (int mt = 0; mt < 2; mt++) {
#pragma unroll
            for (int nt = 0; nt < 4; nt++) {
                int r0 = m0 + warp_m + mt * 16 + (lane >> 2);
                int c0 = warp_n + nt * 8 + (lane & 3) * 2;
                *(float2*)(dst + (size_t)r0 * FF + c0) =
                    make_float2(acc[mt][nt][0], acc[mt][nt][1]);
                *(float2*)(dst + (size_t)(r0 + 8) * FF + c0) =
                    make_float2(acc[mt][nt][2], acc[mt][nt][3]);
            }
        }
    }
}

// ---------------------------------------------------------------------------
// Final fused kernel: out = (K0*x + K1*sin(yp) + K2*sin(yn) + acc2) @ W + bias
// ---------------------------------------------------------------------------
__global__ void final_kernel(const float* __restrict__ x, const float* __restrict__ w,
                             const float* __restrict__ bias, float* __restrict__ out) {
    __shared__ float wsm[FF * OO];
    __shared__ float vsm[4 * FF];
    int tid = threadIdx.x;
#pragma unroll
    for (int j = 0; j < 16; j++) wsm[tid + j * 256] = w[tid + j * 256];
    int r = tid >> 6, f = tid & 63;
    int i = blockIdx.x * 4 + r;
    int idx = i * FF + f;
    float yp = 0.f, yn = 0.f;
#pragma unroll
    for (int p = 0; p < 8; p++) yp += g_ypart[p][idx];
#pragma unroll
    for (int p = 8; p < 16; p++) yn += g_ypart[p][idx];
    float v = K0c * x[idx] + K1c * sinf(yp) + K2c * sinf(yn) + g_acc2[idx];
    vsm[r * FF + f] = v;
    __syncthreads();
    int o = f;
    float acc = bias[o];
#pragma unroll
    for (int ff = 0; ff < FF; ff++)
        acc += vsm[r * FF + ff] * wsm[ff * OO + o];
    out[i * OO + o] = acc;
}

// ---------------------------------------------------------------------------
// Launch
// ---------------------------------------------------------------------------
extern "C" void kernel_launch(void* const* d_in, const int* in_sizes, int n_in,
                              void* d_out, int out_size) {
    const float* x    = (const float*)d_in[0];
    const float* lapP = (const float*)d_in[1];
    const float* lapN = (const float*)d_in[2];
    const float* inc  = (const float*)d_in[3];
    const float* w    = (const float*)d_in[4];
    const float* bias = (const float*)d_in[5];
    float* out = (float*)d_out;

    cudaFuncSetAttribute(gemm_persist_kernel,
                         cudaFuncAttributeMaxDynamicSharedMemorySize, GEMM_SMEM);

    split_x_kernel<<<(NN * FF) / 256, 256>>>(x);
    gemm_persist_kernel<<<592, 128, GEMM_SMEM>>>(lapP, lapN, inc);
    struct_kernel<<<SS / 8, 256>>>(x);
    final_kernel<<<NN / 4, 256>>>(x, w, bias, out);
}

// round 10
// speedup vs baseline: 1.5681x; 1.1279x over previous
#include <cuda_runtime.h>
#include <cuda_bf16.h>
#include <stdint.h>

// Problem constants
#define NN 8192      // nodes
#define SS 8192      // structures
#define FF 64        // features
#define OO 64        // out features
#define K0c 0.5f
#define K1c 0.05f
#define K2c (-0.05f)
#define K3c 0.05f

// ---------------------------------------------------------------------------
// Device scratch (static allocation — allowed)
// ---------------------------------------------------------------------------
__device__ __nv_bfloat16 g_xThi[FF * NN];   // x^T split hi  [f][k]
__device__ __nv_bfloat16 g_xTlo[FF * NN];   // x^T split lo  [f][k]
__device__ float g_ypart[16][NN * FF];      // [mat*8 + ksplit][n][f]
__device__ int   g_cnt[SS];
__device__ int   g_members[SS * 10];
__device__ float g_acc2[NN * FF];

// ---------------------------------------------------------------------------
// portable PTX helpers (no sm_103a-only features)
// ---------------------------------------------------------------------------
#define LDSM_X4(r0, r1, r2, r3, addr) \
    asm volatile("ldmatrix.sync.aligned.m8n8.x4.shared.b16 {%0,%1,%2,%3}, [%4];" \
                 : "=r"(r0), "=r"(r1), "=r"(r2), "=r"(r3) : "r"(addr))

#define MMA16816(c, a, b0, b1) \
    asm volatile("mma.sync.aligned.m16n8k16.row.col.f32.bf16.bf16.f32 " \
                 "{%0,%1,%2,%3}, {%4,%5,%6,%7}, {%8,%9}, {%0,%1,%2,%3};" \
                 : "+f"((c)[0]), "+f"((c)[1]), "+f"((c)[2]), "+f"((c)[3]) \
                 : "r"((a)[0]), "r"((a)[1]), "r"((a)[2]), "r"((a)[3]), \
                   "r"(b0), "r"(b1))

#define CP_ASYNC16(dst, src) \
    asm volatile("cp.async.cg.shared.global [%0], [%1], 16;" \
                 :: "r"(dst), "l"(src) : "memory")
#define CP_COMMIT() asm volatile("cp.async.commit_group;" ::: "memory")
#define CP_WAIT1()  asm volatile("cp.async.wait_group 1;" ::: "memory")

__device__ __forceinline__ uint32_t smem_u32(const void* p) {
    return (uint32_t)__cvta_generic_to_shared(p);
}

// ---------------------------------------------------------------------------
// Kernel: split x into transposed bf16 hi/lo pairs + zero accumulators
// ---------------------------------------------------------------------------
__global__ void split_x_kernel(const float* __restrict__ x) {
    int t = blockIdx.x * 256 + threadIdx.x;       // 0 .. NN*FF-1
    int i = t >> 6, f = t & 63;
    float v = x[t];
    __nv_bfloat16 h = __float2bfloat16(v);
    float r = v - __bfloat162float(h);
    g_xThi[f * NN + i] = h;
    g_xTlo[f * NN + i] = __float2bfloat16(r);
    g_acc2[t] = 0.f;
    if (t < SS) g_cnt[t] = 0;
}

// ---------------------------------------------------------------------------
// Kernel: per-structure tanh term + scatter into acc2
// ---------------------------------------------------------------------------
__global__ void struct_kernel(const float* __restrict__ x) {
    int wid = threadIdx.x >> 5, lid = threadIdx.x & 31;
    int s = blockIdx.x * 8 + wid;
    int m = g_cnt[s];
    if (m != 3 && m != 4 && m != 10) return;
    int mem[10];
    int first = 0x7FFFFFFF;
#pragma unroll 10
    for (int j = 0; j < 10; j++) {
        if (j < m) {
            mem[j] = g_members[s * 10 + j];
            first = min(first, mem[j]);
        }
    }
    float sa = 0.f, sb = 0.f;
    for (int j = 0; j < m; j++) {
        const float* xr = x + mem[j] * FF;
        sa += xr[lid];
        sb += xr[lid + 32];
    }
    const float* xf = x + first * FF;
    float fm = (float)m;
    float ta = tanhf(fm * xf[lid]      - sa) * K3c;
    float tb = tanhf(fm * xf[lid + 32] - sb) * K3c;
    for (int j = 0; j < m; j++) {
        atomicAdd(&g_acc2[mem[j] * FF + lid],      ta);
        atomicAdd(&g_acc2[mem[j] * FF + 32 + lid], tb);
    }
}

// ---------------------------------------------------------------------------
// Fused GEMM + interleaved incidence extraction (R6 skeleton).
// GEMM: y = Lap @ x, mma.sync bf16-split (3 terms), cp.async 3-stage pipe.
// BM=64, BN=64, TKC=32, 128 threads (4 warps, 2x2), 4 CTAs/SM.
// Each CTA extracts a 128KB inc slice, 2 float4/thread per mainloop iter.
// grid = 2048 (128 mtiles x 8 ksplits x 2 matrices).
// ---------------------------------------------------------------------------
#define TKC 32
#define KSPLIT 8
#define KPER (NN / KSPLIT)          // 1024
#define GITERS (KPER / TKC)         // 32
#define NSTAGE 3
// stage: A fp32 64 rows x 160B = 10240; Bhi 64x64B = 4096; Blo 4096
#define A_ROW_B 160
#define B_OFF   10240
#define BL_OFF  14336
#define STAGE_BYTES 18432
#define GEMM_SMEM (NSTAGE * STAGE_BYTES)

// SW64 swizzle for 64B rows: chunk c (16B) at row r -> c ^ ((r>>1)&3)
#define SW64C(r, c) (((c) ^ (((r) >> 1) & 3)) << 4)

// truncation split: hi = packed upper-16 of each fp32 (1 PRMT),
// lo = rn_bf16x2(a - hi)  (2 AND + 2 FADD + 1 CVT)
__device__ __forceinline__ void split_trunc2(float2 v, uint32_t& h, uint32_t& l) {
    uint32_t r0 = __float_as_uint(v.x), r1 = __float_as_uint(v.y);
    uint32_t hp;
    asm("prmt.b32 %0, %1, %2, 0x7632;" : "=r"(hp) : "r"(r0), "r"(r1));
    float a0 = __uint_as_float(r0 & 0xFFFF0000u);
    float a1 = __uint_as_float(r1 & 0xFFFF0000u);
    __nv_bfloat162 ll = __floats2bfloat162_rn(v.x - a0, v.y - a1);
    h = hp;
    l = *(uint32_t*)&ll;
}

__device__ __forceinline__ void issue_stage(const float* __restrict__ A,
                                            int m0, int k0, int tid,
                                            uint32_t sstage) {
    // A: 64 rows x 32 fp32 (128B = 8 x 16B chunks) -> 512 chunks, 4/thread
#pragma unroll
    for (int j = 0; j < 4; j++) {
        int q = tid + j * 128;
        int row = q >> 3, c = q & 7;
        uint32_t dst = sstage + row * A_ROW_B + c * 16;
        const float* src = A + (size_t)(m0 + row) * NN + k0 + c * 4;
        CP_ASYNC16(dst, src);
    }
    // B hi/lo: 64 rows x 32 bf16 = 64B/row, SW64 packed -> 256 chunks each
#pragma unroll
    for (int j = 0; j < 2; j++) {
        int q = tid + j * 128;
        int row = q >> 2, c = q & 3;
        uint32_t sw = (uint32_t)(row * 64 + SW64C(row, c));
        const char* srch = (const char*)(g_xThi + (size_t)row * NN + k0 + c * 8);
        const char* srcl = (const char*)(g_xTlo + (size_t)row * NN + k0 + c * 8);
        CP_ASYNC16(sstage + B_OFF + sw, srch);
        CP_ASYNC16(sstage + BL_OFF + sw, srcl);
    }
    CP_COMMIT();
}

__global__ void __launch_bounds__(128, 4)
gemm_extract_kernel(const float* __restrict__ lapP, const float* __restrict__ lapN,
                    const float* __restrict__ inc) {
    extern __shared__ char smem[];
    const int tid = threadIdx.x;
    const int wid = tid >> 5;
    const int lane = tid & 31;
    const int bid = blockIdx.x;
    const int mat = bid >> 10;
    const int rest = bid & 1023;
    const int ks = rest & 7;
    const int mtile = rest >> 3;
    const float* A = mat ? lapN : lapP;
    float* dst = g_ypart[mat * 8 + ks];
    const int m0 = mtile * 64;
    const int kb = ks * KPER;

    const int warp_m = (wid & 1) * 32;   // 2 warps along M
    const int warp_n = (wid >> 1) * 32;  // 2 warps along N

    const uint32_t sbase = smem_u32(smem);
    const float4* inc4 = (const float4*)inc;
    const int inc_base = bid * 8192;

    float acc[2][4][4];
#pragma unroll
    for (int mt = 0; mt < 2; mt++)
#pragma unroll
        for (int nt = 0; nt < 4; nt++)
#pragma unroll
            for (int j = 0; j < 4; j++) acc[mt][nt][j] = 0.f;

    // prologue: issue first NSTAGE-1 stages
    issue_stage(A, m0, kb, tid, sbase);
    issue_stage(A, m0, kb + TKC, tid, sbase + STAGE_BYTES);

    // ---- GEMM mainloop with interleaved incidence extraction ----
    for (int it = 0; it < GITERS; ++it) {
        CP_WAIT1();            // 2 groups pending -> stage `it` resident
        __syncthreads();

        if (it + NSTAGE - 1 < GITERS)
            issue_stage(A, m0, kb + (it + NSTAGE - 1) * TKC, tid,
                        sbase + ((it + NSTAGE - 1) % NSTAGE) * STAGE_BYTES);
        else
            CP_COMMIT();       // empty group keeps pending count at 2

        // interleaved extraction: 2 float4 per thread per iteration
        {
            int q0 = inc_base + it * 256 + tid;
            float4 v0 = __ldcs(inc4 + q0);
            float4 v1 = __ldcs(inc4 + q0 + 128);
#pragma unroll
            for (int jj = 0; jj < 2; jj++) {
                int q = q0 + jj * 128;
                float4 v = jj ? v1 : v0;
                int e = q * 4;
                int i = e >> 13;        // node row
                int sc = e & 8191;      // structure col
                float vv[4] = {v.x, v.y, v.z, v.w};
#pragma unroll
                for (int u = 0; u < 4; u++) {
                    if (vv[u] != 0.0f) {
                        int p = atomicAdd(&g_cnt[sc + u], 1);
                        if (p < 10) g_members[(sc + u) * 10 + p] = i;
                    }
                }
            }
        }

        const uint32_t sstage = sbase + (it % NSTAGE) * STAGE_BYTES;
        const char* sa = smem + (it % NSTAGE) * STAGE_BYTES;

#pragma unroll
        for (int kc = 0; kc < 2; kc++) {
            // ---- A fragments: LDS fp32 + truncation split ----
            uint32_t ah[2][4], al[2][4];
#pragma unroll
            for (int mt = 0; mt < 2; mt++) {
                int row0 = warp_m + mt * 16 + (lane >> 2);
                int kbyt = kc * 64 + (lane & 3) * 8;
                const char* p = sa + row0 * A_ROW_B + kbyt;
                float2 v0 = *(const float2*)(p);
                float2 v1 = *(const float2*)(p + 8 * A_ROW_B);
                float2 v2 = *(const float2*)(p + 32);
                float2 v3 = *(const float2*)(p + 8 * A_ROW_B + 32);
                split_trunc2(v0, ah[mt][0], al[mt][0]);
                split_trunc2(v1, ah[mt][1], al[mt][1]);
                split_trunc2(v2, ah[mt][2], al[mt][2]);
                split_trunc2(v3, ah[mt][3], al[mt][3]);
            }
            // ---- B fragments via ldmatrix from SW64-packed rows ----
            uint32_t bh[2][4], bl[2][4];
#pragma unroll
            for (int nt2 = 0; nt2 < 2; nt2++) {
                uint32_t grp = lane >> 3;
                uint32_t nrow = warp_n + nt2 * 16 + (grp >> 1) * 8 + (lane & 7);
                uint32_t c = kc * 2 + (grp & 1);
                uint32_t off = nrow * 64 + SW64C(nrow, c);
                LDSM_X4(bh[nt2][0], bh[nt2][1], bh[nt2][2], bh[nt2][3],
                        sstage + B_OFF + off);
                LDSM_X4(bl[nt2][0], bl[nt2][1], bl[nt2][2], bl[nt2][3],
                        sstage + BL_OFF + off);
            }
#pragma unroll
            for (int mt = 0; mt < 2; mt++) {
#pragma unroll
                for (int nt = 0; nt < 4; nt++) {
                    int n2 = nt >> 1, p = (nt & 1) * 2;
                    MMA16816(acc[mt][nt], ah[mt], bh[n2][p], bh[n2][p + 1]);
                    MMA16816(acc[mt][nt], ah[mt], bl[n2][p], bl[n2][p + 1]);
                    MMA16816(acc[mt][nt], al[mt], bh[n2][p], bh[n2][p + 1]);
                }
            }
        }
    }

    // ---- epilogue: write partial results ----
#pragma unroll
    for (int mt = 0; mt < 2; mt++) {
#pragma unroll
        for (int nt = 0; nt < 4; nt++) {
            int r0 = m0 + warp_m + mt * 16 + (lane >> 2);
            int c0 = warp_n + nt * 8 + (lane & 3) * 2;
            *(float2*)(dst + (size_t)r0 * FF + c0) =
                make_float2(acc[mt][nt][0], acc[mt][nt][1]);
            *(float2*)(dst + (size_t)(r0 + 8) * FF + c0) =
                make_float2(acc[mt][nt][2], acc[mt][nt][3]);
        }
    }
}

// ---------------------------------------------------------------------------
// Final fused kernel: out = (K0*x + K1*sin(yp) + K2*sin(yn) + acc2) @ W + bias
// ---------------------------------------------------------------------------
__global__ void final_kernel(const float* __restrict__ x, const float* __restrict__ w,
                             const float* __restrict__ bias, float* __restrict__ out) {
    __shared__ float wsm[FF * OO];
    __shared__ float vsm[4 * FF];
    int tid = threadIdx.x;
#pragma unroll
    for (int j = 0; j < 16; j++) wsm[tid + j * 256] = w[tid + j * 256];
    int r = tid >> 6, f = tid & 63;
    int i = blockIdx.x * 4 + r;
    int idx = i * FF + f;
    float yp = 0.f, yn = 0.f;
#pragma unroll
    for (int p = 0; p < 8; p++) yp += g_ypart[p][idx];
#pragma unroll
    for (int p = 8; p < 16; p++) yn += g_ypart[p][idx];
    float v = K0c * x[idx] + K1c * sinf(yp) + K2c * sinf(yn) + g_acc2[idx];
    vsm[r * FF + f] = v;
    __syncthreads();
    int o = f;
    float acc = bias[o];
#pragma unroll
    for (int ff = 0; ff < FF; ff++)
        acc += vsm[r * FF + ff] * wsm[ff * OO + o];
    out[i * OO + o] = acc;
}

// ---------------------------------------------------------------------------
// Launch
// ---------------------------------------------------------------------------
extern "C" void kernel_launch(void* const* d_in, const int* in_sizes, int n_in,
                              void* d_out, int out_size) {
    const float* x    = (const float*)d_in[0];
    const float* lapP = (const float*)d_in[1];
    const float* lapN = (const float*)d_in[2];
    const float* inc  = (const float*)d_in[3];
    const float* w    = (const float*)d_in[4];
    const float* bias = (const float*)d_in[5];
    float* out = (float*)d_out;

    cudaFuncSetAttribute(gemm_extract_kernel,
                         cudaFuncAttributeMaxDynamicSharedMemorySize, GEMM_SMEM);

    split_x_kernel<<<(NN * FF) / 256, 256>>>(x);
    gemm_extract_kernel<<<2048, 128, GEMM_SMEM>>>(lapP, lapN, inc);
    struct_kernel<<<SS / 8, 256>>>(x);
    final_kernel<<<NN / 4, 256>>>(x, w, bias, out);
}